// round 15
// baseline (speedup 1.0000x reference)
#include <cuda_runtime.h>

#define S 128
#define H 64
#define GRIDR 64
#define NMAX 8192
#define MLP_GRID 444
#define MLP_BLK 128

__device__ int      g_cnt;                 // statically zero; composite re-zeros each run
__device__ float4   g_pts[NMAX * S];       // (px,py,pz, id-as-float-bits), compacted
__device__ float4   g_rgba_c[NMAX * S];    // (r,g,b,alpha), compacted (same index space)
__device__ unsigned g_mask[NMAX * 4];      // 128-bit active mask per ray
__device__ int      g_roff[NMAX];          // per-ray start offset in compacted arrays

// ---- f16 helpers ----
__device__ __forceinline__ float f16_round(float v) {
    unsigned short h;
    asm("cvt.rn.f16.f32 %0, %1;" : "=h"(h) : "f"(v));
    float r;
    asm("cvt.f32.f16 %0, %1;" : "=f"(r) : "h"(h));
    return r;
}
__device__ __forceinline__ unsigned f16x2_of(float lo_v, float hi_v) {
    unsigned r;
    asm("cvt.rn.f16x2.f32 %0, %1, %2;" : "=r"(r) : "f"(hi_v), "f"(lo_v));
    return r;
}
__device__ __forceinline__ void mma16816(
    float& d0, float& d1, float& d2, float& d3,
    unsigned a0, unsigned a1, unsigned a2, unsigned a3,
    unsigned b0, unsigned b1,
    float c0, float c1, float c2, float c3)
{
    asm("mma.sync.aligned.m16n8k16.row.col.f32.f16.f16.f32 "
        "{%0,%1,%2,%3}, {%4,%5,%6,%7}, {%8,%9}, {%10,%11,%12,%13};"
        : "=f"(d0), "=f"(d1), "=f"(d2), "=f"(d3)
        : "r"(a0), "r"(a1), "r"(a2), "r"(a3), "r"(b0), "r"(b1),
          "f"(c0), "f"(c1), "f"(c2), "f"(c3));
}

// spread 16 bits to even positions of 32
__device__ __forceinline__ unsigned bit_spread16(unsigned x) {
    x &= 0xFFFFu;
    x = (x | (x << 8)) & 0x00FF00FFu;
    x = (x | (x << 4)) & 0x0F0F0F0Fu;
    x = (x | (x << 2)) & 0x33333333u;
    x = (x | (x << 1)) & 0x55555555u;
    return x;
}

// ================= kernel 1: occupancy + compaction, 2 samples/thread =================
// block = 256 threads = 4 rays; warp = 64 consecutive samples of one ray
__global__ void __launch_bounds__(256) compact_kernel(
    const float* __restrict__ rays_o, const float* __restrict__ rays_d,
    const float* __restrict__ near_, const float* __restrict__ far_,
    const float* __restrict__ jitter, const float* __restrict__ density,
    int nrays)
{
    __shared__ int warp_base[8];

    const int tid = threadIdx.x;
    const int wid = tid >> 5;          // 0..7
    const int lane = tid & 31;
    const int rayq = wid >> 1;         // ray-in-block 0..3
    const int wir = wid & 1;           // warp-in-ray
    const int ray = blockIdx.x * 4 + rayq;
    const int t = (wir << 5) + lane;   // thread-in-ray 0..63 → samples 2t, 2t+1

    bool a0 = false, a1 = false;
    float p0x = 0.f, p0y = 0.f, p0z = 0.f;
    float p1x = 0.f, p1y = 0.f, p1z = 0.f;

    if (ray < nrays) {
        const float ox = rays_o[ray * 3 + 0], oy = rays_o[ray * 3 + 1], oz = rays_o[ray * 3 + 2];
        const float dx = rays_d[ray * 3 + 0], dy = rays_d[ray * 3 + 1], dz = rays_d[ray * 3 + 2];
        const float nr = near_[ray], fr = far_[ray];
        const float step = (fr - nr) * (1.0f / (float)S);
        const float2 jt = *(const float2*)&jitter[ray * S + 2 * t];

        #pragma unroll
        for (int q = 0; q < 2; q++) {
            const int s = 2 * t + q;
            const float z = nr + (float)s * step;
            const float wx = ox + z * dx;
            const float wy = oy + z * dy;
            const float wz = oz + z * dz;
            const float fx = ((wx + 1.25f) * 0.4f) * 64.0f;
            const float fy = ((wy + 1.55f) * 0.4f) * 64.0f;
            const float fz = ((wz + 1.25f) * 0.4f) * 64.0f;
            const int ix = (int)floorf(fx);
            const int iy = (int)floorf(fy);
            const int iz = (int)floorf(fz);
            const bool inb = (ix >= 0) & (ix < GRIDR) & (iy >= 0) & (iy < GRIDR) &
                             (iz >= 0) & (iz < GRIDR);
            bool act = false;
            if (inb) act = __ldg(&density[(ix * GRIDR + iy) * GRIDR + iz]) > 0.5f;

            float zv = act ? z : 0.0f;
            zv += (q ? jt.y : jt.x) * step;

            const float px = ox + zv * dx;
            const float py = oy + zv * dy;
            const float pz = oz + zv * dz;
            if (q == 0) { a0 = act; p0x = px; p0y = py; p0z = pz; }
            else        { a1 = act; p1x = px; p1y = py; p1z = pz; }
        }
    }

    const unsigned b0 = __ballot_sync(0xffffffffu, a0);   // even samples
    const unsigned b1 = __ballot_sync(0xffffffffu, a1);   // odd samples
    if (lane == 0) warp_base[wid] = __popc(b0) + __popc(b1);
    __syncthreads();
    if (tid == 0) {
        int sum = 0;
        #pragma unroll
        for (int w = 0; w < 8; w++) { int c = warp_base[w]; warp_base[w] = sum; sum += c; }
        const int base = atomicAdd(&g_cnt, sum);
        #pragma unroll
        for (int w = 0; w < 8; w++) warp_base[w] += base;
    }
    __syncthreads();

    if (ray < nrays) {
        if (t == 0) g_roff[ray] = warp_base[rayq * 2];

        // mask words: lane h<2 builds word for samples [64*wir+32h, +32)
        if (lane < 2) {
            const unsigned xe = bit_spread16(b0 >> (16 * lane));
            const unsigned xo = bit_spread16(b1 >> (16 * lane));
            g_mask[ray * 4 + wir * 2 + lane] = xe | (xo << 1);
        }

        const unsigned lm = (1u << lane) - 1u;
        const int before = __popc(b0 & lm) + __popc(b1 & lm);
        const int base = warp_base[wid] + before;
        if (a0) g_pts[base] = make_float4(p0x, p0y, p0z, __int_as_float((ray << 7) | (2 * t)));
        if (a1) g_pts[base + (a0 ? 1 : 0)] =
            make_float4(p1x, p1y, p1z, __int_as_float((ray << 7) | (2 * t + 1)));
    }
}

// ================= kernel 2: tensor-core MLP (trimmed residual mmas) =================
__global__ void __launch_bounds__(MLP_BLK, 3) mlp_kernel(
    const float* __restrict__ near_, const float* __restrict__ far_,
    const float* __restrict__ W1, const float* __restrict__ b1,
    const float* __restrict__ W2, const float* __restrict__ b2,
    const float* __restrict__ Wsig, const float* __restrict__ bsig,
    const float* __restrict__ Wrgb, const float* __restrict__ brgb)
{
    __shared__ __align__(16) uint4 sW1f[8][32];
    __shared__ __align__(16) uint4 sW2f[32][32];
    __shared__ __align__(16) uint4 sB3f[4][32];
    __shared__ float s_b2[H];
    __shared__ float s_bias4[4];

    const int tid = threadIdx.x;

    for (int e = tid; e < 44 * 32; e += MLP_BLK) {
        const int lane = e & 31, tile = e >> 5;
        const int q = lane & 3, gr = lane >> 2;
        float v[4];
        if (tile < 8) {
            const int n = tile * 8 + gr;
            #pragma unroll
            for (int j = 0; j < 4; j++) {
                const int k = ((j >> 1) << 3) + 2 * q + (j & 1);
                v[j] = (k < 3) ? W1[k * H + n] : (k == 3 ? b1[n] : 0.0f);
            }
        } else if (tile < 40) {
            const int t = tile - 8;
            const int kt = t >> 3, nt = t & 7;
            const int n = nt * 8 + gr;
            #pragma unroll
            for (int j = 0; j < 4; j++) {
                const int k = kt * 16 + ((j >> 1) << 3) + 2 * q + (j & 1);
                v[j] = W2[k * H + n];
            }
        } else {
            const int kt = tile - 40;
            const int n = gr;
            #pragma unroll
            for (int j = 0; j < 4; j++) {
                const int k = kt * 16 + ((j >> 1) << 3) + 2 * q + (j & 1);
                v[j] = (n == 0) ? Wsig[k] : (n < 4 ? Wrgb[k * 3 + (n - 1)] : 0.0f);
            }
        }
        const float h0 = f16_round(v[0]), h1v = f16_round(v[1]);
        const float h2 = f16_round(v[2]), h3v = f16_round(v[3]);
        uint4 pk;
        pk.x = f16x2_of(h0, h1v);
        pk.y = f16x2_of(h2, h3v);
        pk.z = f16x2_of(v[0] - h0, v[1] - h1v);
        pk.w = f16x2_of(v[2] - h2, v[3] - h3v);
        if (tile < 8)       sW1f[tile][lane] = pk;
        else if (tile < 40) sW2f[tile - 8][lane] = pk;
        else                sB3f[tile - 40][lane] = pk;
    }
    for (int i = tid; i < H; i += MLP_BLK) s_b2[i] = b2[i];
    if (tid == 0) {
        s_bias4[0] = bsig[0]; s_bias4[1] = brgb[0];
        s_bias4[2] = brgb[1]; s_bias4[3] = brgb[2];
    }
    __syncthreads();

    const int cnt = g_cnt;
    const int warp = tid >> 5, lane = tid & 31;
    const int q = lane & 3, gr = lane >> 2;
    const float* P = (const float*)g_pts;
    const int stride = gridDim.x * 4 * 16;

    for (int base = (blockIdx.x * 4 + warp) * 16; base < cnt; base += stride) {
        const int i0 = min(base + gr, cnt - 1);
        const int i1 = min(base + gr + 8, cnt - 1);

        unsigned a1h0 = 0, a1h1 = 0, a1l0 = 0, a1l1 = 0;
        if (q < 2) {
            float u0, v0, u1, v1;
            if (q == 0) {
                float2 t0 = *(const float2*)&P[i0 * 4];
                float2 t1 = *(const float2*)&P[i1 * 4];
                u0 = t0.x; v0 = t0.y; u1 = t1.x; v1 = t1.y;
            } else {
                u0 = P[i0 * 4 + 2]; v0 = 1.0f;
                u1 = P[i1 * 4 + 2]; v1 = 1.0f;
            }
            const float u0h = f16_round(u0), v0h = f16_round(v0);
            const float u1h = f16_round(u1), v1h = f16_round(v1);
            a1h0 = f16x2_of(u0h, v0h);  a1l0 = f16x2_of(u0 - u0h, v0 - v0h);
            a1h1 = f16x2_of(u1h, v1h);  a1l1 = f16x2_of(u1 - u1h, v1 - v1h);
        }

        // ---- layer 1: full 3-mma precision (cheap; errors would propagate) ----
        float c1[8][4];
        #pragma unroll
        for (int nt = 0; nt < 8; nt++) {
            const uint4 w = sW1f[nt][lane];
            float d0 = 0.f, d1 = 0.f, d2 = 0.f, d3 = 0.f;
            mma16816(d0, d1, d2, d3, a1h0, a1h1, 0u, 0u, w.x, w.y, d0, d1, d2, d3);
            mma16816(d0, d1, d2, d3, a1h0, a1h1, 0u, 0u, w.z, w.w, d0, d1, d2, d3);
            mma16816(d0, d1, d2, d3, a1l0, a1l1, 0u, 0u, w.x, w.y, d0, d1, d2, d3);
            c1[nt][0] = fmaxf(d0, 0.f); c1[nt][1] = fmaxf(d1, 0.f);
            c1[nt][2] = fmaxf(d2, 0.f); c1[nt][3] = fmaxf(d3, 0.f);
        }

        // ---- pack h (hi only; B stays exact via Bh+Bl mmas) ----
        unsigned a2h[4][4];
        #pragma unroll
        for (int kt = 0; kt < 4; kt++) {
            #pragma unroll
            for (int r = 0; r < 4; r++) {
                const int nt = 2 * kt + (r >> 1);
                a2h[kt][r] = f16x2_of(f16_round(c1[nt][(r & 1) ? 2 : 0]),
                                      f16_round(c1[nt][(r & 1) ? 3 : 1]));
            }
        }

        // ---- layer 2: 2 mmas/tile (Ah·Bh + Ah·Bl) ----
        float c2[8][4];
        #pragma unroll
        for (int nt = 0; nt < 8; nt++) { c2[nt][0] = c2[nt][1] = c2[nt][2] = c2[nt][3] = 0.f; }
        #pragma unroll
        for (int kt = 0; kt < 4; kt++) {
            #pragma unroll
            for (int nt = 0; nt < 8; nt++) {
                const uint4 w = sW2f[kt * 8 + nt][lane];
                mma16816(c2[nt][0], c2[nt][1], c2[nt][2], c2[nt][3],
                         a2h[kt][0], a2h[kt][1], a2h[kt][2], a2h[kt][3], w.x, w.y,
                         c2[nt][0], c2[nt][1], c2[nt][2], c2[nt][3]);
                mma16816(c2[nt][0], c2[nt][1], c2[nt][2], c2[nt][3],
                         a2h[kt][0], a2h[kt][1], a2h[kt][2], a2h[kt][3], w.z, w.w,
                         c2[nt][0], c2[nt][1], c2[nt][2], c2[nt][3]);
            }
        }

        // ---- +b2, relu, pack y (hi only) ----
        unsigned a3h[4][4];
        {
            float y[8][4];
            #pragma unroll
            for (int nt = 0; nt < 8; nt++) {
                const float2 bb = *(const float2*)&s_b2[nt * 8 + 2 * q];
                y[nt][0] = fmaxf(c2[nt][0] + bb.x, 0.f);
                y[nt][1] = fmaxf(c2[nt][1] + bb.y, 0.f);
                y[nt][2] = fmaxf(c2[nt][2] + bb.x, 0.f);
                y[nt][3] = fmaxf(c2[nt][3] + bb.y, 0.f);
            }
            #pragma unroll
            for (int kt = 0; kt < 4; kt++) {
                #pragma unroll
                for (int r = 0; r < 4; r++) {
                    const int nt = 2 * kt + (r >> 1);
                    a3h[kt][r] = f16x2_of(f16_round(y[nt][(r & 1) ? 2 : 0]),
                                          f16_round(y[nt][(r & 1) ? 3 : 1]));
                }
            }
        }

        // ---- heads: 2 mmas/kt ----
        float o0 = 0.f, o1 = 0.f, o2 = 0.f, o3 = 0.f;
        #pragma unroll
        for (int kt = 0; kt < 4; kt++) {
            const uint4 w = sB3f[kt][lane];
            mma16816(o0, o1, o2, o3, a3h[kt][0], a3h[kt][1], a3h[kt][2], a3h[kt][3],
                     w.x, w.y, o0, o1, o2, o3);
            mma16816(o0, o1, o2, o3, a3h[kt][0], a3h[kt][1], a3h[kt][2], a3h[kt][3],
                     w.z, w.w, o0, o1, o2, o3);
        }

        const float p0 = __shfl_xor_sync(0xffffffffu, o0, 1);
        const float p1 = __shfl_xor_sync(0xffffffffu, o1, 1);
        const float p2 = __shfl_xor_sync(0xffffffffu, o2, 1);
        const float p3 = __shfl_xor_sync(0xffffffffu, o3, 1);
        if (q == 0) {
            #pragma unroll
            for (int half = 0; half < 2; half++) {
                const int i = base + gr + half * 8;
                if (i < cnt) {
                    const float sig = (half ? o2 : o0) + s_bias4[0];
                    const float cr  = (half ? o3 : o1) + s_bias4[1];
                    const float cg  = (half ? p2 : p0) + s_bias4[2];
                    const float cb  = (half ? p3 : p1) + s_bias4[3];
                    const int id = __float_as_int(P[i * 4 + 3]);
                    const int ray = id >> 7;
                    const float step = (__ldg(&far_[ray]) - __ldg(&near_[ray])) * (1.0f / (float)S);
                    const float tau = fmaxf(sig, 0.0f) * step;
                    const float alpha = 1.0f - __expf(-tau);
                    const float r = __fdividef(1.0f, 1.0f + __expf(-cr));
                    const float g = __fdividef(1.0f, 1.0f + __expf(-cg));
                    const float b = __fdividef(1.0f, 1.0f + __expf(-cb));
                    g_rgba_c[i] = make_float4(r, g, b, alpha);
                }
            }
        }
    }
}

// ================= kernel 3: per-ray composite over compacted rgba =================
__global__ void __launch_bounds__(256) composite_kernel(
    float* __restrict__ out, int nrays)
{
    const int tid = threadIdx.x;
    const int wid = tid >> 5;
    const int lane = tid & 31;
    const int ray = blockIdx.x * 8 + wid;

    if (blockIdx.x == 0 && tid == 0) g_cnt = 0;

    if (ray >= nrays) return;

    const unsigned m0 = __ldg(&g_mask[ray * 4 + 0]);
    const unsigned m1 = __ldg(&g_mask[ray * 4 + 1]);
    const unsigned m2 = __ldg(&g_mask[ray * 4 + 2]);
    const unsigned m3 = __ldg(&g_mask[ray * 4 + 3]);
    const int roff = __ldg(&g_roff[ray]);

    const int wsel = lane >> 3;
    const int p0c = __popc(m0), p1c = __popc(m1), p2c = __popc(m2);
    int rank = (wsel > 0 ? p0c : 0) + (wsel > 1 ? p1c : 0) + (wsel > 2 ? p2c : 0);
    const unsigned mw = (wsel == 0) ? m0 : (wsel == 1) ? m1 : (wsel == 2) ? m2 : m3;
    const int bit0 = (lane & 7) * 4;
    rank += __popc(mw & ((1u << bit0) - 1u));

    float4 v[4];
    float ta[4];
    float pl = 1.0f;
    #pragma unroll
    for (int q = 0; q < 4; q++) {
        const bool act = (mw >> (bit0 + q)) & 1u;
        if (act) { v[q] = g_rgba_c[roff + rank]; rank++; }
        else       v[q] = make_float4(0.f, 0.f, 0.f, 0.f);
        ta[q] = 1.0f - v[q].w + 1e-10f;
        pl *= ta[q];
    }
    float inc = pl;
    #pragma unroll
    for (int off = 1; off < 32; off <<= 1) {
        const float t = __shfl_up_sync(0xffffffffu, inc, off);
        if (lane >= off) inc *= t;
    }
    const float total = __shfl_sync(0xffffffffu, inc, 31);
    float pre = __shfl_up_sync(0xffffffffu, inc, 1);
    if (lane == 0) pre = 1.0f;

    float T = pre, acr = 0.0f, acg = 0.0f, acb = 0.0f;
    #pragma unroll
    for (int q = 0; q < 4; q++) {
        const float w = v[q].w * T;
        acr = fmaf(w, v[q].x, acr);
        acg = fmaf(w, v[q].y, acg);
        acb = fmaf(w, v[q].z, acb);
        T *= ta[q];
    }
    #pragma unroll
    for (int off = 16; off >= 1; off >>= 1) {
        acr += __shfl_xor_sync(0xffffffffu, acr, off);
        acg += __shfl_xor_sync(0xffffffffu, acg, off);
        acb += __shfl_xor_sync(0xffffffffu, acb, off);
    }
    if (lane == 0) {
        out[ray * 3 + 0] = acr + total;
        out[ray * 3 + 1] = acg + total;
        out[ray * 3 + 2] = acb + total;
    }
}

extern "C" void kernel_launch(void* const* d_in, const int* in_sizes, int n_in,
                              void* d_out, int out_size) {
    const float* rays_o  = (const float*)d_in[0];
    const float* rays_d  = (const float*)d_in[1];
    const float* near_   = (const float*)d_in[2];
    const float* far_    = (const float*)d_in[3];
    const float* jitter  = (const float*)d_in[4];
    const float* density = (const float*)d_in[5];
    const float* W1      = (const float*)d_in[6];
    const float* b1      = (const float*)d_in[7];
    const float* W2      = (const float*)d_in[8];
    const float* b2      = (const float*)d_in[9];
    const float* Wsig    = (const float*)d_in[10];
    const float* bsig    = (const float*)d_in[11];
    const float* Wrgb    = (const float*)d_in[12];
    const float* brgb    = (const float*)d_in[13];
    float* out = (float*)d_out;

    const int nrays = in_sizes[2];

    compact_kernel<<<(nrays + 3) / 4, 256>>>(rays_o, rays_d, near_, far_,
                                             jitter, density, nrays);
    mlp_kernel<<<MLP_GRID, MLP_BLK>>>(near_, far_, W1, b1, W2, b2,
                                      Wsig, bsig, Wrgb, brgb);
    composite_kernel<<<(nrays + 7) / 8, 256>>>(out, nrays);
}

// round 16
// speedup vs baseline: 1.4371x; 1.4371x over previous
#include <cuda_runtime.h>

#define S 128
#define H 64
#define GRIDR 64
#define NMAX 8192
#define MLP_GRID 444
#define MLP_BLK 128

__device__ int      g_cnt;                 // statically zero; composite re-zeros each run
__device__ float4   g_pts[NMAX * S];       // (px,py,pz, id-as-float-bits), compacted
__device__ float4   g_rgba[NMAX * S];      // (r,g,b,alpha), id-indexed; only active slots written
__device__ unsigned g_mask[NMAX * 4];      // 128-bit active mask per ray

// ---- f16 helpers ----
__device__ __forceinline__ float f16_round(float v) {
    unsigned short h;
    asm("cvt.rn.f16.f32 %0, %1;" : "=h"(h) : "f"(v));
    float r;
    asm("cvt.f32.f16 %0, %1;" : "=f"(r) : "h"(h));
    return r;
}
__device__ __forceinline__ unsigned f16x2_of(float lo_v, float hi_v) {
    unsigned r;
    asm("cvt.rn.f16x2.f32 %0, %1, %2;" : "=r"(r) : "f"(hi_v), "f"(lo_v));
    return r;
}
__device__ __forceinline__ void mma16816(
    float& d0, float& d1, float& d2, float& d3,
    unsigned a0, unsigned a1, unsigned a2, unsigned a3,
    unsigned b0, unsigned b1,
    float c0, float c1, float c2, float c3)
{
    asm("mma.sync.aligned.m16n8k16.row.col.f32.f16.f16.f32 "
        "{%0,%1,%2,%3}, {%4,%5,%6,%7}, {%8,%9}, {%10,%11,%12,%13};"
        : "=f"(d0), "=f"(d1), "=f"(d2), "=f"(d3)
        : "r"(a0), "r"(a1), "r"(a2), "r"(a3), "r"(b0), "r"(b1),
          "f"(c0), "f"(c1), "f"(c2), "f"(c3));
}

// ================= kernel 1: occupancy test + global compaction + mask =================
__global__ void __launch_bounds__(256) compact_kernel(
    const float* __restrict__ rays_o, const float* __restrict__ rays_d,
    const float* __restrict__ near_, const float* __restrict__ far_,
    const float* __restrict__ jitter, const float* __restrict__ density,
    int nrays)
{
    __shared__ int warp_base[8];

    const int tid = threadIdx.x;
    const int q   = tid >> 7;
    const int s   = tid & 127;
    const int ray = blockIdx.x * 2 + q;
    const int wid = tid >> 5;
    const int lane = tid & 31;

    bool active = false;
    float px = 0.f, py = 0.f, pz = 0.f;
    int id = 0;

    if (ray < nrays) {
        const float ox = rays_o[ray * 3 + 0], oy = rays_o[ray * 3 + 1], oz = rays_o[ray * 3 + 2];
        const float dx = rays_d[ray * 3 + 0], dy = rays_d[ray * 3 + 1], dz = rays_d[ray * 3 + 2];
        const float nr = near_[ray], fr = far_[ray];
        const float step = (fr - nr) * (1.0f / (float)S);

        const float z = nr + (float)s * step;
        const float px0 = ox + z * dx;
        const float py0 = oy + z * dy;
        const float pz0 = oz + z * dz;
        const float fx = ((px0 + 1.25f) * 0.4f) * 64.0f;
        const float fy = ((py0 + 1.55f) * 0.4f) * 64.0f;
        const float fz = ((pz0 + 1.25f) * 0.4f) * 64.0f;
        const int ix = (int)floorf(fx);
        const int iy = (int)floorf(fy);
        const int iz = (int)floorf(fz);
        const bool inb = (ix >= 0) & (ix < GRIDR) & (iy >= 0) & (iy < GRIDR) &
                         (iz >= 0) & (iz < GRIDR);
        if (inb) active = __ldg(&density[(ix * GRIDR + iy) * GRIDR + iz]) > 0.5f;

        float zv = active ? z : 0.0f;
        zv += jitter[ray * S + s] * step;

        px = ox + zv * dx;
        py = oy + zv * dy;
        pz = oz + zv * dz;
        id = (ray << 7) | s;
    }

    const unsigned ballot = __ballot_sync(0xffffffffu, active);
    if (lane == 0 && ray < nrays) g_mask[ray * 4 + (wid & 3)] = ballot;

    if (lane == 0) warp_base[wid] = __popc(ballot);
    __syncthreads();
    if (tid == 0) {
        int sum = 0;
        #pragma unroll
        for (int w = 0; w < 8; w++) { int c = warp_base[w]; warp_base[w] = sum; sum += c; }
        const int base = atomicAdd(&g_cnt, sum);
        #pragma unroll
        for (int w = 0; w < 8; w++) warp_base[w] += base;
    }
    __syncthreads();
    if (active) {
        const int idx = warp_base[wid] + __popc(ballot & ((1u << lane) - 1u));
        g_pts[idx] = make_float4(px, py, pz, __int_as_float(id));
    }
}

// ================= kernel 2: tensor-core MLP (trimmed residual mmas) =================
__global__ void __launch_bounds__(MLP_BLK, 3) mlp_kernel(
    const float* __restrict__ near_, const float* __restrict__ far_,
    const float* __restrict__ W1, const float* __restrict__ b1,
    const float* __restrict__ W2, const float* __restrict__ b2,
    const float* __restrict__ Wsig, const float* __restrict__ bsig,
    const float* __restrict__ Wrgb, const float* __restrict__ brgb)
{
    __shared__ __align__(16) uint4 sW1f[8][32];
    __shared__ __align__(16) uint4 sW2f[32][32];
    __shared__ __align__(16) uint4 sB3f[4][32];
    __shared__ float s_b2[H];
    __shared__ float s_bias4[4];

    const int tid = threadIdx.x;

    for (int e = tid; e < 44 * 32; e += MLP_BLK) {
        const int lane = e & 31, tile = e >> 5;
        const int q = lane & 3, gr = lane >> 2;
        float v[4];
        if (tile < 8) {
            const int n = tile * 8 + gr;
            #pragma unroll
            for (int j = 0; j < 4; j++) {
                const int k = ((j >> 1) << 3) + 2 * q + (j & 1);
                v[j] = (k < 3) ? W1[k * H + n] : (k == 3 ? b1[n] : 0.0f);
            }
        } else if (tile < 40) {
            const int t = tile - 8;
            const int kt = t >> 3, nt = t & 7;
            const int n = nt * 8 + gr;
            #pragma unroll
            for (int j = 0; j < 4; j++) {
                const int k = kt * 16 + ((j >> 1) << 3) + 2 * q + (j & 1);
                v[j] = W2[k * H + n];
            }
        } else {
            const int kt = tile - 40;
            const int n = gr;
            #pragma unroll
            for (int j = 0; j < 4; j++) {
                const int k = kt * 16 + ((j >> 1) << 3) + 2 * q + (j & 1);
                v[j] = (n == 0) ? Wsig[k] : (n < 4 ? Wrgb[k * 3 + (n - 1)] : 0.0f);
            }
        }
        const float h0 = f16_round(v[0]), h1v = f16_round(v[1]);
        const float h2 = f16_round(v[2]), h3v = f16_round(v[3]);
        uint4 pk;
        pk.x = f16x2_of(h0, h1v);
        pk.y = f16x2_of(h2, h3v);
        pk.z = f16x2_of(v[0] - h0, v[1] - h1v);
        pk.w = f16x2_of(v[2] - h2, v[3] - h3v);
        if (tile < 8)       sW1f[tile][lane] = pk;
        else if (tile < 40) sW2f[tile - 8][lane] = pk;
        else                sB3f[tile - 40][lane] = pk;
    }
    for (int i = tid; i < H; i += MLP_BLK) s_b2[i] = b2[i];
    if (tid == 0) {
        s_bias4[0] = bsig[0]; s_bias4[1] = brgb[0];
        s_bias4[2] = brgb[1]; s_bias4[3] = brgb[2];
    }
    __syncthreads();

    const int cnt = g_cnt;
    const int warp = tid >> 5, lane = tid & 31;
    const int q = lane & 3, gr = lane >> 2;
    const float* P = (const float*)g_pts;
    const int stride = gridDim.x * 4 * 16;

    for (int base = (blockIdx.x * 4 + warp) * 16; base < cnt; base += stride) {
        const int i0 = min(base + gr, cnt - 1);
        const int i1 = min(base + gr + 8, cnt - 1);

        unsigned a1h0 = 0, a1h1 = 0, a1l0 = 0, a1l1 = 0;
        if (q < 2) {
            float u0, v0, u1, v1;
            if (q == 0) {
                float2 t0 = *(const float2*)&P[i0 * 4];
                float2 t1 = *(const float2*)&P[i1 * 4];
                u0 = t0.x; v0 = t0.y; u1 = t1.x; v1 = t1.y;
            } else {
                u0 = P[i0 * 4 + 2]; v0 = 1.0f;
                u1 = P[i1 * 4 + 2]; v1 = 1.0f;
            }
            const float u0h = f16_round(u0), v0h = f16_round(v0);
            const float u1h = f16_round(u1), v1h = f16_round(v1);
            a1h0 = f16x2_of(u0h, v0h);  a1l0 = f16x2_of(u0 - u0h, v0 - v0h);
            a1h1 = f16x2_of(u1h, v1h);  a1l1 = f16x2_of(u1 - u1h, v1 - v1h);
        }

        // ---- layer 1: full 3-mma precision (errors here propagate) ----
        float c1[8][4];
        #pragma unroll
        for (int nt = 0; nt < 8; nt++) {
            const uint4 w = sW1f[nt][lane];
            float d0 = 0.f, d1 = 0.f, d2 = 0.f, d3 = 0.f;
            mma16816(d0, d1, d2, d3, a1h0, a1h1, 0u, 0u, w.x, w.y, d0, d1, d2, d3);
            mma16816(d0, d1, d2, d3, a1h0, a1h1, 0u, 0u, w.z, w.w, d0, d1, d2, d3);
            mma16816(d0, d1, d2, d3, a1l0, a1l1, 0u, 0u, w.x, w.y, d0, d1, d2, d3);
            c1[nt][0] = fmaxf(d0, 0.f); c1[nt][1] = fmaxf(d1, 0.f);
            c1[nt][2] = fmaxf(d2, 0.f); c1[nt][3] = fmaxf(d3, 0.f);
        }

        // ---- pack h (hi only; B stays exact via Bh+Bl mmas) ----
        unsigned a2h[4][4];
        #pragma unroll
        for (int kt = 0; kt < 4; kt++) {
            #pragma unroll
            for (int r = 0; r < 4; r++) {
                const int nt = 2 * kt + (r >> 1);
                a2h[kt][r] = f16x2_of(f16_round(c1[nt][(r & 1) ? 2 : 0]),
                                      f16_round(c1[nt][(r & 1) ? 3 : 1]));
            }
        }

        // ---- layer 2: 2 mmas/tile (Ah·Bh + Ah·Bl) ----
        float c2[8][4];
        #pragma unroll
        for (int nt = 0; nt < 8; nt++) { c2[nt][0] = c2[nt][1] = c2[nt][2] = c2[nt][3] = 0.f; }
        #pragma unroll
        for (int kt = 0; kt < 4; kt++) {
            #pragma unroll
            for (int nt = 0; nt < 8; nt++) {
                const uint4 w = sW2f[kt * 8 + nt][lane];
                mma16816(c2[nt][0], c2[nt][1], c2[nt][2], c2[nt][3],
                         a2h[kt][0], a2h[kt][1], a2h[kt][2], a2h[kt][3], w.x, w.y,
                         c2[nt][0], c2[nt][1], c2[nt][2], c2[nt][3]);
                mma16816(c2[nt][0], c2[nt][1], c2[nt][2], c2[nt][3],
                         a2h[kt][0], a2h[kt][1], a2h[kt][2], a2h[kt][3], w.z, w.w,
                         c2[nt][0], c2[nt][1], c2[nt][2], c2[nt][3]);
            }
        }

        // ---- +b2, relu, pack y (hi only) ----
        unsigned a3h[4][4];
        {
            float y[8][4];
            #pragma unroll
            for (int nt = 0; nt < 8; nt++) {
                const float2 bb = *(const float2*)&s_b2[nt * 8 + 2 * q];
                y[nt][0] = fmaxf(c2[nt][0] + bb.x, 0.f);
                y[nt][1] = fmaxf(c2[nt][1] + bb.y, 0.f);
                y[nt][2] = fmaxf(c2[nt][2] + bb.x, 0.f);
                y[nt][3] = fmaxf(c2[nt][3] + bb.y, 0.f);
            }
            #pragma unroll
            for (int kt = 0; kt < 4; kt++) {
                #pragma unroll
                for (int r = 0; r < 4; r++) {
                    const int nt = 2 * kt + (r >> 1);
                    a3h[kt][r] = f16x2_of(f16_round(y[nt][(r & 1) ? 2 : 0]),
                                          f16_round(y[nt][(r & 1) ? 3 : 1]));
                }
            }
        }

        // ---- heads: 2 mmas/kt ----
        float o0 = 0.f, o1 = 0.f, o2 = 0.f, o3 = 0.f;
        #pragma unroll
        for (int kt = 0; kt < 4; kt++) {
            const uint4 w = sB3f[kt][lane];
            mma16816(o0, o1, o2, o3, a3h[kt][0], a3h[kt][1], a3h[kt][2], a3h[kt][3],
                     w.x, w.y, o0, o1, o2, o3);
            mma16816(o0, o1, o2, o3, a3h[kt][0], a3h[kt][1], a3h[kt][2], a3h[kt][3],
                     w.z, w.w, o0, o1, o2, o3);
        }

        const float p0 = __shfl_xor_sync(0xffffffffu, o0, 1);
        const float p1 = __shfl_xor_sync(0xffffffffu, o1, 1);
        const float p2 = __shfl_xor_sync(0xffffffffu, o2, 1);
        const float p3 = __shfl_xor_sync(0xffffffffu, o3, 1);
        if (q == 0) {
            #pragma unroll
            for (int half = 0; half < 2; half++) {
                const int i = base + gr + half * 8;
                if (i < cnt) {
                    const float sig = (half ? o2 : o0) + s_bias4[0];
                    const float cr  = (half ? o3 : o1) + s_bias4[1];
                    const float cg  = (half ? p2 : p0) + s_bias4[2];
                    const float cb  = (half ? p3 : p1) + s_bias4[3];
                    const int id = __float_as_int(P[i * 4 + 3]);
                    const int ray = id >> 7;
                    const float step = (__ldg(&far_[ray]) - __ldg(&near_[ray])) * (1.0f / (float)S);
                    const float tau = fmaxf(sig, 0.0f) * step;
                    const float alpha = 1.0f - __expf(-tau);
                    const float r = __fdividef(1.0f, 1.0f + __expf(-cr));
                    const float g = __fdividef(1.0f, 1.0f + __expf(-cg));
                    const float b = __fdividef(1.0f, 1.0f + __expf(-cb));
                    g_rgba[id] = make_float4(r, g, b, alpha);
                }
            }
        }
    }
}

// ================= kernel 3: per-ray masked alpha composite (+ counter reset) =================
__global__ void __launch_bounds__(256) composite_kernel(
    float* __restrict__ out, int nrays)
{
    const int tid = threadIdx.x;
    const int wid = tid >> 5;
    const int lane = tid & 31;
    const int ray = blockIdx.x * 8 + wid;

    if (blockIdx.x == 0 && tid == 0) g_cnt = 0;   // reset for next replay

    if (ray >= nrays) return;

    const float4* rp = &g_rgba[ray << 7];
    const unsigned m = g_mask[ray * 4 + (lane >> 3)];

    float4 v[4];
    float ta[4];
    float pl = 1.0f;
    #pragma unroll
    for (int q = 0; q < 4; q++) {
        const unsigned bit = ((lane & 7) << 2) + q;
        if ((m >> bit) & 1u) v[q] = rp[lane * 4 + q];
        else                 v[q] = make_float4(0.f, 0.f, 0.f, 0.f);
        ta[q] = 1.0f - v[q].w + 1e-10f;
        pl *= ta[q];
    }
    float inc = pl;
    #pragma unroll
    for (int off = 1; off < 32; off <<= 1) {
        const float t = __shfl_up_sync(0xffffffffu, inc, off);
        if (lane >= off) inc *= t;
    }
    const float total = __shfl_sync(0xffffffffu, inc, 31);
    float pre = __shfl_up_sync(0xffffffffu, inc, 1);
    if (lane == 0) pre = 1.0f;

    float T = pre, acr = 0.0f, acg = 0.0f, acb = 0.0f;
    #pragma unroll
    for (int q = 0; q < 4; q++) {
        const float w = v[q].w * T;
        acr = fmaf(w, v[q].x, acr);
        acg = fmaf(w, v[q].y, acg);
        acb = fmaf(w, v[q].z, acb);
        T *= ta[q];
    }
    #pragma unroll
    for (int off = 16; off >= 1; off >>= 1) {
        acr += __shfl_xor_sync(0xffffffffu, acr, off);
        acg += __shfl_xor_sync(0xffffffffu, acg, off);
        acb += __shfl_xor_sync(0xffffffffu, acb, off);
    }
    if (lane == 0) {
        out[ray * 3 + 0] = acr + total;
        out[ray * 3 + 1] = acg + total;
        out[ray * 3 + 2] = acb + total;
    }
}

extern "C" void kernel_launch(void* const* d_in, const int* in_sizes, int n_in,
                              void* d_out, int out_size) {
    const float* rays_o  = (const float*)d_in[0];
    const float* rays_d  = (const float*)d_in[1];
    const float* near_   = (const float*)d_in[2];
    const float* far_    = (const float*)d_in[3];
    const float* jitter  = (const float*)d_in[4];
    const float* density = (const float*)d_in[5];
    const float* W1      = (const float*)d_in[6];
    const float* b1      = (const float*)d_in[7];
    const float* W2      = (const float*)d_in[8];
    const float* b2      = (const float*)d_in[9];
    const float* Wsig    = (const float*)d_in[10];
    const float* bsig    = (const float*)d_in[11];
    const float* Wrgb    = (const float*)d_in[12];
    const float* brgb    = (const float*)d_in[13];
    float* out = (float*)d_out;

    const int nrays = in_sizes[2];

    compact_kernel<<<(nrays + 1) / 2, 256>>>(rays_o, rays_d, near_, far_,
                                             jitter, density, nrays);
    mlp_kernel<<<MLP_GRID, MLP_BLK>>>(near_, far_, W1, b1, W2, b2,
                                      Wsig, bsig, Wrgb, brgb);
    composite_kernel<<<(nrays + 7) / 8, 256>>>(out, nrays);
}